// round 2
// baseline (speedup 1.0000x reference)
#include <cuda_runtime.h>
#include <cuda_bf16.h>

// Problem constants
#define B_   4
#define L_   256
#define DK   48      // D*K
#define D_   8
#define K_   6
#define A_   64
#define O_   64
#define DA   512     // D*A
#define CH   8       // i-values processed per phase in the pair kernel

// Scratch (device globals: allocation-free)
__device__ float g_L1[B_ * L_ * DK];   // input_1 . anchors[:, :, 0:64]
__device__ float g_L2[B_ * L_ * DK];   // input_2 . anchors[:, :, 64:128]
__device__ float g_L3[L_ * DK];        // pos_emb . anchors[:, :, 128:192]
__device__ float g_S [B_ * L_ * DA];   // per-(b,j) accumulated address distribution

// ---------------------------------------------------------------------------
// Kernel A: precompute partial logits. grid = B*L blocks, 192 threads.
// ---------------------------------------------------------------------------
__global__ void precompute_kernel(const float* __restrict__ in1,
                                  const float* __restrict__ in2,
                                  const float* __restrict__ pos,
                                  const float* __restrict__ anchors) {
    __shared__ float sA[DK * 193];   // anchors rows padded to 193 (conflict-free)
    __shared__ float sx1[64], sx2[64], sp[64];
    const int tid = threadIdx.x;
    const int bid = blockIdx.x;
    const int b = bid >> 8;
    const int l = bid & 255;

    #pragma unroll 1
    for (int it = 0; it < DK; it++)
        sA[it * 193 + tid] = anchors[it * 192 + tid];

    if (tid < 64)        sx1[tid]       = in1[(b * L_ + l) * 64 + tid];
    else if (tid < 128)  sx2[tid - 64]  = in2[(b * L_ + l) * 64 + (tid - 64)];
    else                 sp [tid - 128] = pos[l * 64 + (tid - 128)];
    __syncthreads();

    if (tid < 48) {
        const float* a = &sA[tid * 193];
        float acc = 0.f;
        #pragma unroll 8
        for (int f = 0; f < 64; f++) acc = fmaf(sx1[f], a[f], acc);
        g_L1[(b * L_ + l) * DK + tid] = acc;
    } else if (tid < 96) {
        const int dk = tid - 48;
        const float* a = &sA[dk * 193 + 64];
        float acc = 0.f;
        #pragma unroll 8
        for (int f = 0; f < 64; f++) acc = fmaf(sx2[f], a[f], acc);
        g_L2[(b * L_ + l) * DK + dk] = acc;
    } else if (tid < 144 && b == 0) {
        const int dk = tid - 96;
        const float* a = &sA[dk * 193 + 128];
        float acc = 0.f;
        #pragma unroll 8
        for (int f = 0; f < 64; f++) acc = fmaf(sp[f], a[f], acc);
        g_L3[l * DK + dk] = acc;
    }
}

// ---------------------------------------------------------------------------
// Kernel B: pair loop. grid = (L, B), 512 threads.
//   thread -> group g = tid>>6 (which i of the CH-chunk), tg = tid&63,
//   d = tg>>3, hi = tg&7 (address bits 3..5). Thread accumulates 8 addresses.
// Double-buffered sigmoid staging, 1 barrier per phase, register prefetch.
// ---------------------------------------------------------------------------
__global__ void __launch_bounds__(512)
pair_kernel() {
    __shared__ float sL2[DK];
    __shared__ float q[2][CH][DK][2];   // [buf][i-slot][d*6+k][bit0:1-p, bit1:p]
    __shared__ float s4[CH][DA];        // per-group partial S for final reduce

    const int tid = threadIdx.x;
    const int j = (L_ - 1) - blockIdx.x;   // big-j blocks first (load balance)
    const int b = blockIdx.y;

    if (tid < DK) sL2[tid] = g_L2[(b * L_ + j) * DK + tid];

    const int g  = tid >> 6;
    const int tg = tid & 63;
    const int d  = tg >> 3;
    const int hi = tg & 7;

    const bool stager = tid < CH * DK;        // 384 staging threads
    const int ii = tid / DK;                  // 0..7
    const int dk = tid - ii * DK;             // 0..47

    float acc[8];
    #pragma unroll
    for (int m = 0; m < 8; m++) acc[m] = 0.f;

    const int nph = (j + CH - 1) / CH;

    const float* pL1 = &g_L1[(b * L_) * DK + dk];
    const float* pL3 = &g_L3[dk];

    float lg1 = 0.f, lg3 = 0.f;
    if (stager && ii < j) {                    // preload phase 0
        lg1 = pL1[ii * DK];
        lg3 = pL3[(j - ii) * DK];
    }
    __syncthreads();                           // sL2 ready

    for (int ph = 0; ph < nph; ph++) {
        const int buf = ph & 1;
        const int i0  = ph * CH;

        // stage: sigmoid from prefetched regs into q[buf]
        if (stager) {
            const int i = i0 + ii;
            if (i < j) {
                const float logit = sL2[dk] + lg1 + lg3;
                const float e   = __expf(-logit);
                const float inv = __fdividef(1.0f, 1.0f + e);  // p(bit=1)
                q[buf][ii][dk][1] = inv;
                q[buf][ii][dk][0] = e * inv;                   // p(bit=0)
            }
            // prefetch next phase (LDG latency hidden behind consume)
            const int in = i0 + CH + ii;
            if (in < j) {
                lg1 = pL1[in * DK];
                lg3 = pL3[(j - in) * DK];
            }
        }
        __syncthreads();                       // q[buf] ready

        // consume: product tree over address bits, 8 addresses / thread
        const int i = i0 + g;
        if (i < j) {
            const float* qb = &q[buf][g][d * K_][0];
            const float2 q0 = *(const float2*)(qb + 0);
            const float2 q1 = *(const float2*)(qb + 2);
            const float2 q2 = *(const float2*)(qb + 4);
            const float q3 = qb[6  + (hi & 1)];
            const float q4 = qb[8  + ((hi >> 1) & 1)];
            const float q5 = qb[10 + ((hi >> 2) & 1)];

            const float bse = q3 * q4 * q5;
            const float u0 = bse * q0.x, u1 = bse * q0.y;
            const float v00 = u0 * q1.x, v01 = u1 * q1.x;
            const float v10 = u0 * q1.y, v11 = u1 * q1.y;
            acc[0] = fmaf(v00, q2.x, acc[0]);
            acc[1] = fmaf(v01, q2.x, acc[1]);
            acc[2] = fmaf(v10, q2.x, acc[2]);
            acc[3] = fmaf(v11, q2.x, acc[3]);
            acc[4] = fmaf(v00, q2.y, acc[4]);
            acc[5] = fmaf(v01, q2.y, acc[5]);
            acc[6] = fmaf(v10, q2.y, acc[6]);
            acc[7] = fmaf(v11, q2.y, acc[7]);
        }
        // NOTE: no second barrier needed — double buffer guarantees
        // consume(ph) finishes before store(ph+2) touches the same buffer.
        // But store(ph+1) must not race consume(ph) on a DIFFERENT buffer: OK.
        // The single barrier above orders store->consume within a phase, and
        // the next phase's barrier orders consume(ph) before store(ph+2).
    }

    // reduce 8 group copies of S and write to global
    #pragma unroll
    for (int m = 0; m < 8; m++) s4[g][tg * 8 + m] = acc[m];
    __syncthreads();
    float ssum = 0.f;
    #pragma unroll
    for (int gg = 0; gg < CH; gg++) ssum += s4[gg][tid];
    g_S[(b * L_ + j) * DA + tid] = ssum;
}

// ---------------------------------------------------------------------------
// Kernel C: out[row, o] = sum_da S[row, da] * W[da, o].
// grid = 16 blocks (64 rows each), 256 threads: og = tid>>6 (16 cols), rr = tid&63.
// ---------------------------------------------------------------------------
__global__ void __launch_bounds__(256)
final_gemm(const float* __restrict__ W, float* __restrict__ out) {
    __shared__ float sW[64 * 64];
    __shared__ float sS[64 * 65];
    const int tid = threadIdx.x;
    const int r0  = blockIdx.x * 64;
    const int rr  = tid & 63;
    const int og  = tid >> 6;

    float acc[16];
    #pragma unroll
    for (int m = 0; m < 16; m++) acc[m] = 0.f;

    for (int c = 0; c < 8; c++) {
        const int dac = c * 64;
        // W chunk: contiguous 4096 floats
        const float4* Wv = (const float4*)(W + dac * 64);
        float4* sWv = (float4*)sW;
        #pragma unroll
        for (int t = tid; t < 1024; t += 256) sWv[t] = Wv[t];
        // S chunk: 64 rows x 64 cols (row stride 512 in global)
        #pragma unroll
        for (int t = tid; t < 1024; t += 256) {
            const int r  = t >> 4;
            const int c4 = (t & 15) << 2;
            const float4 v = *(const float4*)(&g_S[(r0 + r) * DA + dac + c4]);
            float* dst = &sS[r * 65 + c4];
            dst[0] = v.x; dst[1] = v.y; dst[2] = v.z; dst[3] = v.w;
        }
        __syncthreads();

        #pragma unroll 4
        for (int kk = 0; kk < 64; kk++) {
            const float s = sS[rr * 65 + kk];
            const float4* w4 = (const float4*)(&sW[kk * 64 + og * 16]);
            const float4 w0 = w4[0], w1 = w4[1], w2 = w4[2], w3 = w4[3];
            acc[0]  = fmaf(s, w0.x, acc[0]);
            acc[1]  = fmaf(s, w0.y, acc[1]);
            acc[2]  = fmaf(s, w0.z, acc[2]);
            acc[3]  = fmaf(s, w0.w, acc[3]);
            acc[4]  = fmaf(s, w1.x, acc[4]);
            acc[5]  = fmaf(s, w1.y, acc[5]);
            acc[6]  = fmaf(s, w1.z, acc[6]);
            acc[7]  = fmaf(s, w1.w, acc[7]);
            acc[8]  = fmaf(s, w2.x, acc[8]);
            acc[9]  = fmaf(s, w2.y, acc[9]);
            acc[10] = fmaf(s, w2.z, acc[10]);
            acc[11] = fmaf(s, w2.w, acc[11]);
            acc[12] = fmaf(s, w3.x, acc[12]);
            acc[13] = fmaf(s, w3.y, acc[13]);
            acc[14] = fmaf(s, w3.z, acc[14]);
            acc[15] = fmaf(s, w3.w, acc[15]);
        }
        __syncthreads();
    }

    float* po = out + (r0 + rr) * O_ + og * 16;
    ((float4*)po)[0] = make_float4(acc[0],  acc[1],  acc[2],  acc[3]);
    ((float4*)po)[1] = make_float4(acc[4],  acc[5],  acc[6],  acc[7]);
    ((float4*)po)[2] = make_float4(acc[8],  acc[9],  acc[10], acc[11]);
    ((float4*)po)[3] = make_float4(acc[12], acc[13], acc[14], acc[15]);
}

// ---------------------------------------------------------------------------
extern "C" void kernel_launch(void* const* d_in, const int* in_sizes, int n_in,
                              void* d_out, int out_size) {
    const float* in1     = (const float*)d_in[0];
    const float* in2     = (const float*)d_in[1];
    const float* pos     = (const float*)d_in[2];
    const float* anchors = (const float*)d_in[3];
    const float* lut     = (const float*)d_in[4];
    float* out = (float*)d_out;

    precompute_kernel<<<B_ * L_, 192>>>(in1, in2, pos, anchors);
    pair_kernel<<<dim3(L_, B_), 512>>>();
    final_gemm<<<(B_ * L_) / 64, 256>>>(lut, out);
}

// round 3
// speedup vs baseline: 2.1769x; 2.1769x over previous
#include <cuda_runtime.h>
#include <cuda_bf16.h>

// Problem constants
#define B_   4
#define L_   256
#define DK   48      // D*K
#define D_   8
#define K_   6
#define A_   64
#define O_   64
#define DA   512     // D*A
#define CH   16      // i-values processed per phase in the pair kernel

// Scratch (device globals: allocation-free)
__device__ float g_L1[B_ * L_ * DK];   // input_1 . anchors[:, :, 0:64]
__device__ float g_L2[B_ * L_ * DK];   // input_2 . anchors[:, :, 64:128]
__device__ float g_L3[L_ * DK];        // pos_emb . anchors[:, :, 128:192]
__device__ float g_S [B_ * L_ * DA];   // per-(b,j) accumulated address distribution

// ---------------------------------------------------------------------------
// Kernel A: partial logits as 3 small GEMMs. 72 blocks x 128 threads.
//   blocks 0-31:  L1 rows (32/block), 32-63: L2, 64-71: L3.
//   Block loads its 48x64 anchor slice + 32x64 x-slab into smem,
//   thread computes a 4-row x 3-col register tile (7 LDS / 12 FMA per f).
// ---------------------------------------------------------------------------
__global__ void __launch_bounds__(128)
precompute_kernel(const float* __restrict__ in1,
                  const float* __restrict__ in2,
                  const float* __restrict__ pos,
                  const float* __restrict__ anchors) {
    __shared__ float sa[DK * 65];    // anchors slice [48][64] padded
    __shared__ float sx[32 * 65];    // x slab [32][64] padded

    const int t  = threadIdx.x;
    const int bi = blockIdx.x;

    int fo, row0;
    const float* src;
    float* dst;
    if (bi < 32)      { fo = 0;   row0 = bi * 32;        src = in1; dst = g_L1; }
    else if (bi < 64) { fo = 64;  row0 = (bi - 32) * 32; src = in2; dst = g_L2; }
    else              { fo = 128; row0 = (bi - 64) * 32; src = pos; dst = g_L3; }

    // anchors slice: 48 x 64 = 768 float4, 6 per thread
    #pragma unroll
    for (int it = 0; it < 6; it++) {
        const int idx = t + it * 128;
        const int c   = idx >> 4;
        const int f4  = (idx & 15) << 2;
        const float4 v = *(const float4*)(anchors + c * 192 + fo + f4);
        float* d = &sa[c * 65 + f4];
        d[0] = v.x; d[1] = v.y; d[2] = v.z; d[3] = v.w;
    }
    // x slab: 32 x 64 = 512 float4, 4 per thread
    #pragma unroll
    for (int it = 0; it < 4; it++) {
        const int idx = t + it * 128;
        const int r   = idx >> 4;
        const int f4  = (idx & 15) << 2;
        const float4 v = *(const float4*)(src + (row0 + r) * 64 + f4);
        float* d = &sx[r * 65 + f4];
        d[0] = v.x; d[1] = v.y; d[2] = v.z; d[3] = v.w;
    }
    __syncthreads();

    const int rg = t & 7;     // rows rg*4 .. rg*4+3
    const int cg = t >> 3;    // cols cg*3 .. cg*3+2

    float acc[4][3];
    #pragma unroll
    for (int r = 0; r < 4; r++)
        #pragma unroll
        for (int c = 0; c < 3; c++) acc[r][c] = 0.f;

    const float* a0 = &sa[(cg * 3 + 0) * 65];
    const float* a1 = &sa[(cg * 3 + 1) * 65];
    const float* a2 = &sa[(cg * 3 + 2) * 65];
    const float* x0 = &sx[(rg * 4 + 0) * 65];
    const float* x1 = &sx[(rg * 4 + 1) * 65];
    const float* x2 = &sx[(rg * 4 + 2) * 65];
    const float* x3 = &sx[(rg * 4 + 3) * 65];

    #pragma unroll 8
    for (int f = 0; f < 64; f++) {
        const float av0 = a0[f], av1 = a1[f], av2 = a2[f];
        const float xv0 = x0[f], xv1 = x1[f], xv2 = x2[f], xv3 = x3[f];
        acc[0][0] = fmaf(xv0, av0, acc[0][0]);
        acc[0][1] = fmaf(xv0, av1, acc[0][1]);
        acc[0][2] = fmaf(xv0, av2, acc[0][2]);
        acc[1][0] = fmaf(xv1, av0, acc[1][0]);
        acc[1][1] = fmaf(xv1, av1, acc[1][1]);
        acc[1][2] = fmaf(xv1, av2, acc[1][2]);
        acc[2][0] = fmaf(xv2, av0, acc[2][0]);
        acc[2][1] = fmaf(xv2, av1, acc[2][1]);
        acc[2][2] = fmaf(xv2, av2, acc[2][2]);
        acc[3][0] = fmaf(xv3, av0, acc[3][0]);
        acc[3][1] = fmaf(xv3, av1, acc[3][1]);
        acc[3][2] = fmaf(xv3, av2, acc[3][2]);
    }

    #pragma unroll
    for (int r = 0; r < 4; r++)
        #pragma unroll
        for (int c = 0; c < 3; c++)
            dst[(row0 + rg * 4 + r) * DK + cg * 3 + c] = acc[r][c];
}

// ---------------------------------------------------------------------------
// Kernel B: pair loop. 1D grid 1024 blocks, 512 threads. CH=16 i per phase.
//   consume: g = tid>>6 handles i-slots g and g+8, 8 addresses each.
//   stage: 384 threads compute sigmoids for 2 slots each, double buffered,
//   register-prefetched L1/L3 loads, single barrier per phase.
// ---------------------------------------------------------------------------
__global__ void __launch_bounds__(512)
pair_kernel() {
    __shared__ float sL2[DK];
    __shared__ float q[2][CH][DK][2];   // 12 KB
    __shared__ float s4[8][DA];         // 16 KB partial-S reduce

    const int tid = threadIdx.x;
    const int bid = blockIdx.x;
    const int b = bid & 3;
    const int j = (L_ - 1) - (bid >> 2);    // big-j blocks scheduled first

    if (tid < DK) sL2[tid] = g_L2[(b * L_ + j) * DK + tid];

    const int g  = tid >> 6;
    const int tg = tid & 63;
    const int d  = tg >> 3;
    const int hi = tg & 7;

    const bool stager = tid < 8 * DK;         // 384 staging threads
    const int ii = tid / DK;                  // 0..7
    const int dk = tid - ii * DK;             // 0..47

    float acc[8];
    #pragma unroll
    for (int m = 0; m < 8; m++) acc[m] = 0.f;

    const int nph = (j + CH - 1) / CH;

    const float* pL1 = &g_L1[(b * L_) * DK + dk];
    const float* pL3 = &g_L3[dk];

    float lg1a = 0.f, lg3a = 0.f, lg1b = 0.f, lg3b = 0.f;
    if (stager) {                              // preload phase 0
        const int ia = ii, ib = ii + 8;
        if (ia < j) { lg1a = pL1[ia * DK]; lg3a = pL3[(j - ia) * DK]; }
        if (ib < j) { lg1b = pL1[ib * DK]; lg3b = pL3[(j - ib) * DK]; }
    }
    __syncthreads();                           // sL2 ready

    for (int ph = 0; ph < nph; ph++) {
        const int buf = ph & 1;
        const int i0  = ph * CH;

        if (stager) {
            const float c2 = sL2[dk];
            const int ia = i0 + ii;
            if (ia < j) {
                const float logit = c2 + lg1a + lg3a;
                const float e   = __expf(-logit);
                const float p1  = __fdividef(1.0f, 1.0f + e);
                q[buf][ii][dk][1] = p1;
                q[buf][ii][dk][0] = e * p1;
            }
            const int ib = i0 + ii + 8;
            if (ib < j) {
                const float logit = c2 + lg1b + lg3b;
                const float e   = __expf(-logit);
                const float p1  = __fdividef(1.0f, 1.0f + e);
                q[buf][ii + 8][dk][1] = p1;
                q[buf][ii + 8][dk][0] = e * p1;
            }
            // prefetch next phase
            const int na = i0 + CH + ii;
            if (na < j) { lg1a = pL1[na * DK]; lg3a = pL3[(j - na) * DK]; }
            const int nb = na + 8;
            if (nb < j) { lg1b = pL1[nb * DK]; lg3b = pL3[(j - nb) * DK]; }
        }
        __syncthreads();                       // q[buf] ready

        // consume: two i-slots (g, g+8), product tree, 8 addresses each
        #pragma unroll
        for (int half = 0; half < 2; half++) {
            const int slot = g + half * 8;
            const int i = i0 + slot;
            if (i < j) {
                const float* qb = &q[buf][slot][d * K_][0];
                const float2 q0 = *(const float2*)(qb + 0);
                const float2 q1 = *(const float2*)(qb + 2);
                const float2 q2 = *(const float2*)(qb + 4);
                const float q3 = qb[6  + (hi & 1)];
                const float q4 = qb[8  + ((hi >> 1) & 1)];
                const float q5 = qb[10 + ((hi >> 2) & 1)];

                const float bse = q3 * q4 * q5;
                const float u0 = bse * q0.x, u1 = bse * q0.y;
                const float v00 = u0 * q1.x, v01 = u1 * q1.x;
                const float v10 = u0 * q1.y, v11 = u1 * q1.y;
                acc[0] = fmaf(v00, q2.x, acc[0]);
                acc[1] = fmaf(v01, q2.x, acc[1]);
                acc[2] = fmaf(v10, q2.x, acc[2]);
                acc[3] = fmaf(v11, q2.x, acc[3]);
                acc[4] = fmaf(v00, q2.y, acc[4]);
                acc[5] = fmaf(v01, q2.y, acc[5]);
                acc[6] = fmaf(v10, q2.y, acc[6]);
                acc[7] = fmaf(v11, q2.y, acc[7]);
            }
        }
        // single barrier per phase: store(ph+2) into buf is ordered after
        // consume(ph) by the barrier at the top of phase ph+1.
    }

    // reduce 8 group copies of S and write to global
    #pragma unroll
    for (int m = 0; m < 8; m++) s4[g][tg * 8 + m] = acc[m];
    __syncthreads();
    float ssum = 0.f;
    #pragma unroll
    for (int gg = 0; gg < 8; gg++) ssum += s4[gg][tid];
    g_S[(b * L_ + j) * DA + tid] = ssum;
}

// ---------------------------------------------------------------------------
// Kernel C: out[row, o] = sum_da S[row, da] * W[da, o].
// 128 blocks (8 rows each) x 256 threads, split-k=2, 2x2 register tiles.
// ---------------------------------------------------------------------------
__global__ void __launch_bounds__(256)
final_gemm(const float* __restrict__ W, float* __restrict__ out) {
    __shared__ float sW[128 * 64];     // 32 KB k-chunk of W
    __shared__ float sS[8][132];       // 8 rows x 128 k (padded)
    __shared__ float red[128][4];

    const int t    = threadIdx.x;
    const int row0 = blockIdx.x * 8;
    const int kh   = t >> 7;           // k-half 0/1
    const int u    = t & 127;
    const int tr   = u >> 5;           // rows tr*2, tr*2+1
    const int tc   = u & 31;           // cols tc*2, tc*2+1

    float a00 = 0.f, a01 = 0.f, a10 = 0.f, a11 = 0.f;

    for (int chnk = 0; chnk < 4; chnk++) {
        const int k0 = chnk * 128;
        // W chunk: 128x64 = 2048 float4, 8 per thread
        const float4* Wv = (const float4*)(W + k0 * 64);
        #pragma unroll
        for (int it = 0; it < 8; it++)
            ((float4*)sW)[t + it * 256] = Wv[t + it * 256];
        // S chunk: 8 rows x 128 = 256 float4, 1 per thread
        {
            const int r  = t >> 5;
            const int c4 = (t & 31) << 2;
            const float4 v = *(const float4*)(&g_S[(row0 + r) * DA + k0 + c4]);
            float* dp = &sS[r][c4];
            dp[0] = v.x; dp[1] = v.y; dp[2] = v.z; dp[3] = v.w;
        }
        __syncthreads();

        const int kb = kh * 64;
        #pragma unroll 8
        for (int kk = 0; kk < 64; kk++) {
            const int k = kb + kk;
            const float2 w = *(const float2*)(&sW[k * 64 + tc * 2]);
            const float s0 = sS[tr * 2][k];
            const float s1 = sS[tr * 2 + 1][k];
            a00 = fmaf(s0, w.x, a00);
            a01 = fmaf(s0, w.y, a01);
            a10 = fmaf(s1, w.x, a10);
            a11 = fmaf(s1, w.y, a11);
        }
        __syncthreads();
    }

    if (kh == 1) {
        red[u][0] = a00; red[u][1] = a01; red[u][2] = a10; red[u][3] = a11;
    }
    __syncthreads();
    if (kh == 0) {
        a00 += red[u][0]; a01 += red[u][1]; a10 += red[u][2]; a11 += red[u][3];
        const int r = row0 + tr * 2, c = tc * 2;
        out[r * O_ + c]           = a00;
        out[r * O_ + c + 1]       = a01;
        out[(r + 1) * O_ + c]     = a10;
        out[(r + 1) * O_ + c + 1] = a11;
    }
}

// ---------------------------------------------------------------------------
extern "C" void kernel_launch(void* const* d_in, const int* in_sizes, int n_in,
                              void* d_out, int out_size) {
    const float* in1     = (const float*)d_in[0];
    const float* in2     = (const float*)d_in[1];
    const float* pos     = (const float*)d_in[2];
    const float* anchors = (const float*)d_in[3];
    const float* lut     = (const float*)d_in[4];
    float* out = (float*)d_out;

    precompute_kernel<<<72, 128>>>(in1, in2, pos, anchors);
    pair_kernel<<<1024, 512>>>();
    final_gemm<<<(B_ * L_) / 8, 256>>>(lut, out);
}